// round 7
// baseline (speedup 1.0000x reference)
#include <cuda_runtime.h>
#include <cooperative_groups.h>
#include <math.h>

namespace cg = cooperative_groups;

#define DD 384
#define HH 128
#define KK 128
#define NT 32
#define NXY 65536
#define MB 8
#define NKNOT 5
#define RC 4            // cluster size
#define J1 (DD / RC)    // 96  (W1 j-slice per CTA)
#define J2 (HH / RC)    // 32
#define J3 (HH / RC)    // 32

// coeff scratch: [c][k][t], t contiguous
__device__ float g_coeff[3 * KK * NT];

// coarse knots (fine-grid indices): 4 steps
__constant__ int c_kn[NKNOT] = {0, 8, 16, 24, 31};

// dynamic smem floats: W slices + state vectors + reduce buffers
#define NW1 (J1 * HH)           // 12288
#define NW2 (J2 * HH)           // 4096
#define NW3 (J3 * DD)           // 12288
#define SMEM_FLOATS (NW1 + NW2 + NW3 + 8 * DD + 2 * HH + 4 * HH + HH + HH + DD)
#define SMEM_BYTES  (SMEM_FLOATS * 4)

__device__ __forceinline__ void store_coeff(int i, int n, float val) {
    int k = i / 3, c = i - 3 * k;
    g_coeff[(c * KK + k) * NT + n] = val;
}

struct Ctx {
    const float *sW1T, *sW2T, *sW3T;
    float *h1, *h2, *part, *red1, *red2, *red3;
    const float *red1p[RC], *red2p[RC], *red3p[RC];  // peer views
    const float *b1, *b2, *b3;
    int r;
};

// vout = W3 * elu(W2 * relu(W1*vin + b1) + b2) + b3
// 512 threads/CTA, RC CTAs each holding a j-slice of the weights in smem.
// Cross-CTA partial-sum all-reduce via DSMEM red buffers.
__device__ __forceinline__ void mlp(cg::cluster_group& cluster,
                                    const float* __restrict__ vin,
                                    float* __restrict__ vout,
                                    const Ctx& cx, int tid)
{
    const int i = tid & 127, p = tid >> 7;
    __syncthreads();                        // vin ready

    // ---- layer 1: local j-slice J1=96, p-split 4 x 24 ----
    {
        const int j0 = p * (J1 / 4);
        float a0 = 0.f, a1 = 0.f;
        #pragma unroll
        for (int j = 0; j < J1 / 4; j += 2) {
            a0 = fmaf(cx.sW1T[(j0 + j    ) * HH + i], vin[cx.r * J1 + j0 + j    ], a0);
            a1 = fmaf(cx.sW1T[(j0 + j + 1) * HH + i], vin[cx.r * J1 + j0 + j + 1], a1);
        }
        cx.part[p * HH + i] = a0 + a1;
    }
    __syncthreads();
    if (tid < HH)
        cx.red1[tid] = (cx.part[tid] + cx.part[HH + tid])
                     + (cx.part[2 * HH + tid] + cx.part[3 * HH + tid]);
    cluster.sync();
    if (tid < HH) {
        float s = cx.b1[tid];
        #pragma unroll
        for (int rr = 0; rr < RC; rr++) s += cx.red1p[rr][tid];
        cx.h1[tid] = fmaxf(s, 0.f);
    }
    __syncthreads();

    // ---- layer 2: local j-slice J2=32, p-split 4 x 8, ELU ----
    {
        const int j0 = p * (J2 / 4);
        float a0 = 0.f, a1 = 0.f;
        #pragma unroll
        for (int j = 0; j < J2 / 4; j += 2) {
            a0 = fmaf(cx.sW2T[(j0 + j    ) * HH + i], cx.h1[cx.r * J2 + j0 + j    ], a0);
            a1 = fmaf(cx.sW2T[(j0 + j + 1) * HH + i], cx.h1[cx.r * J2 + j0 + j + 1], a1);
        }
        cx.part[p * HH + i] = a0 + a1;
    }
    __syncthreads();
    if (tid < HH)
        cx.red2[tid] = (cx.part[tid] + cx.part[HH + tid])
                     + (cx.part[2 * HH + tid] + cx.part[3 * HH + tid]);
    cluster.sync();
    if (tid < HH) {
        float s = cx.b2[tid];
        #pragma unroll
        for (int rr = 0; rr < RC; rr++) s += cx.red2p[rr][tid];
        cx.h2[tid] = s > 0.f ? s : expm1f(s);
    }
    __syncthreads();

    // ---- layer 3: 384 outs, local j-slice J3=32 ----
    if (tid < DD) {
        float a0 = 0.f, a1 = 0.f;
        #pragma unroll
        for (int j = 0; j < J3; j += 2) {
            a0 = fmaf(cx.sW3T[(j    ) * DD + tid], cx.h2[cx.r * J3 + j    ], a0);
            a1 = fmaf(cx.sW3T[(j + 1) * DD + tid], cx.h2[cx.r * J3 + j + 1], a1);
        }
        cx.red3[tid] = a0 + a1;
    }
    cluster.sync();
    if (tid < DD) {
        float s = cx.b3[tid];
        #pragma unroll
        for (int rr = 0; rr < RC; rr++) s += cx.red3p[rr][tid];
        vout[tid] = s;
    }
    __syncthreads();
}

__global__ __launch_bounds__(512, 1) __cluster_dims__(RC, 1, 1)
void integrate_kernel(const float* __restrict__ tarr, const float* __restrict__ y0,
                      const float* __restrict__ W1, const float* __restrict__ b1,
                      const float* __restrict__ W2, const float* __restrict__ b2,
                      const float* __restrict__ W3, const float* __restrict__ b3)
{
    extern __shared__ float smf[];
    cg::cluster_group cluster = cg::this_cluster();
    const int tid = threadIdx.x;
    const int r = (int)cluster.block_rank();

    float* sW1T = smf;
    float* sW2T = sW1T + NW1;
    float* sW3T = sW2T + NW2;
    float* y    = sW3T + NW3;
    float* yold = y + DD;
    float* fold = yold + DD;
    float* v    = fold + DD;
    float* k1   = v + DD;
    float* k2   = k1 + DD;
    float* k3   = k2 + DD;
    float* k4   = k3 + DD;
    float* h1   = k4 + DD;
    float* h2   = h1 + HH;
    float* part = h2 + HH;
    float* red1 = part + 4 * HH;
    float* red2 = red1 + HH;
    float* red3 = red2 + HH;

    Ctx cx;
    cx.sW1T = sW1T; cx.sW2T = sW2T; cx.sW3T = sW3T;
    cx.h1 = h1; cx.h2 = h2; cx.part = part;
    cx.red1 = red1; cx.red2 = red2; cx.red3 = red3;
    cx.b1 = b1; cx.b2 = b2; cx.b3 = b3; cx.r = r;
    #pragma unroll
    for (int rr = 0; rr < RC; rr++) {
        cx.red1p[rr] = (const float*)cluster.map_shared_rank(red1, rr);
        cx.red2p[rr] = (const float*)cluster.map_shared_rank(red2, rr);
        cx.red3p[rr] = (const float*)cluster.map_shared_rank(red3, rr);
    }

    // ---- preload weight slices (transposing), coalesced global reads ----
    for (int idx = tid; idx < NW1; idx += 512) {
        int i = idx / J1, jl = idx - i * J1;
        sW1T[jl * HH + i] = W1[i * DD + r * J1 + jl];
    }
    for (int idx = tid; idx < NW2; idx += 512) {
        int i = idx / J2, jl = idx - i * J2;
        sW2T[jl * HH + i] = W2[i * HH + r * J2 + jl];
    }
    for (int idx = tid; idx < NW3; idx += 512) {
        int i = idx / J3, jl = idx - i * J3;
        sW3T[jl * DD + i] = W3[i * HH + r * J3 + jl];
    }

    for (int i = tid; i < DD; i += 512) {
        float val = y0[i];
        y[i] = val;
        if (r == 0) store_coeff(i, 0, val);
    }

    for (int s = 0; s < NKNOT; s++) {
        // k1 = f(y) at knot s; also f_end of previous coarse interval
        mlp(cluster, y, k1, cx, tid);

        if (s > 0 && r == 0) {
            const int n0 = c_kn[s - 1], n1 = c_kn[s];
            const float t0 = tarr[n0];
            const float hstep = tarr[n1] - t0;
            for (int n = n0 + 1; n < n1; n++) {
                const float th = (tarr[n] - t0) / hstep;
                const float th2 = th * th, th3 = th2 * th;
                const float cy0 = 1.f - 3.f * th2 + 2.f * th3;
                const float cy1 = 3.f * th2 - 2.f * th3;
                const float cf0 = hstep * (th - 2.f * th2 + th3);
                const float cf1 = hstep * (th3 - th2);
                for (int i = tid; i < DD; i += 512) {
                    float val = cy0 * yold[i] + cy1 * y[i]
                              + cf0 * fold[i] + cf1 * k1[i];
                    store_coeff(i, n, val);
                }
            }
            for (int i = tid; i < DD; i += 512)
                store_coeff(i, n1, y[i]);
        }
        if (s == NKNOT - 1) break;

        const float hstep = tarr[c_kn[s + 1]] - tarr[c_kn[s]];
        for (int i = tid; i < DD; i += 512) {
            yold[i] = y[i];
            fold[i] = k1[i];
            v[i] = y[i] + hstep * (1.f / 3.f) * k1[i];
        }

        mlp(cluster, v, k2, cx, tid);
        for (int i = tid; i < DD; i += 512)
            v[i] = y[i] + hstep * (k2[i] - (1.f / 3.f) * k1[i]);

        mlp(cluster, v, k3, cx, tid);
        for (int i = tid; i < DD; i += 512)
            v[i] = y[i] + hstep * (k1[i] - k2[i] + k3[i]);

        mlp(cluster, v, k4, cx, tid);
        for (int i = tid; i < DD; i += 512)
            y[i] = y[i] + hstep * 0.125f * (k1[i] + 3.f * (k2[i] + k3[i]) + k4[i]);
    }
}

// grid: (NXY/256, 3); one pixel per thread, 32 t-accumulators.
// Depth-8 register double-buffer on basis loads -> 8 outstanding lines/warp.
__global__ __launch_bounds__(256, 3)
void einsum_kernel(const float* __restrict__ basis, float* __restrict__ out)
{
    __shared__ __align__(16) float sm[256 * NT];   // 32 KB; first 16 KB doubles as ckt
    float* ckt = sm;
    const int c = blockIdx.y;
    const int px = threadIdx.x;
    const int xy0 = blockIdx.x * 256;
    const int xy = xy0 + px;

    for (int i = px; i < KK * NT; i += 256)
        ckt[i] = g_coeff[c * KK * NT + i];
    __syncthreads();

    float acc[NT];
    #pragma unroll
    for (int t = 0; t < NT; t++) acc[t] = 0.f;

    const float* bp = basis + (size_t)c * NXY + xy;
    const size_t kst = (size_t)3 * NXY;

    float bb[8];
    #pragma unroll
    for (int q = 0; q < 8; q++) bb[q] = __ldcs(bp + q * kst);

    for (int k0 = 0; k0 < KK; k0 += 8) {
        const int k8 = (k0 + 8 < KK) ? k0 + 8 : 0;   // clamp: last prefetch harmless
        float bn[8];
        #pragma unroll
        for (int q = 0; q < 8; q++) bn[q] = __ldcs(bp + (k8 + q) * kst);

        #pragma unroll
        for (int q = 0; q < 8; q++) {
            const float b = bb[q];
            const float4* cw = (const float4*)(ckt + (k0 + q) * NT);
            #pragma unroll
            for (int w = 0; w < 8; w++) {
                float4 cc = cw[w];
                acc[4 * w + 0] = fmaf(cc.x, b, acc[4 * w + 0]);
                acc[4 * w + 1] = fmaf(cc.y, b, acc[4 * w + 1]);
                acc[4 * w + 2] = fmaf(cc.z, b, acc[4 * w + 2]);
                acc[4 * w + 3] = fmaf(cc.w, b, acc[4 * w + 3]);
            }
        }
        #pragma unroll
        for (int q = 0; q < 8; q++) bb[q] = bn[q];
    }
    __syncthreads();            // everyone done reading ckt

    // transpose: sm[t][px] = acc[t]
    #pragma unroll
    for (int t = 0; t < NT; t++) sm[t * 256 + px] = acc[t];
    __syncthreads();

    // vectorized stores: 2048 float4 chunks (32 t x 64 groups), 8 per thread
    #pragma unroll
    for (int q = 0; q < 8; q++) {
        const int ch = q * 256 + px;
        const int t = ch >> 6;
        const int g = ch & 63;
        const float4 v4 = *(const float4*)&sm[t * 256 + 4 * g];
        float* base = out + ((size_t)(t * MB) * 3 + c) * NXY + xy0 + 4 * g;
        #pragma unroll
        for (int m = 0; m < MB; m++)
            __stcs((float4*)(base + (size_t)m * (3 * NXY)), v4);
    }
}

extern "C" void kernel_launch(void* const* d_in, const int* in_sizes, int n_in,
                              void* d_out, int out_size)
{
    // metadata order: grid0, t, init_coeffs, W1, b1, W2, b2, W3, b3, basis
    const float* tarr = (const float*)d_in[1];
    const float* y0   = (const float*)d_in[2];
    const float* W1   = (const float*)d_in[3];
    const float* b1   = (const float*)d_in[4];
    const float* W2   = (const float*)d_in[5];
    const float* b2   = (const float*)d_in[6];
    const float* W3   = (const float*)d_in[7];
    const float* b3   = (const float*)d_in[8];
    const float* basis = (const float*)d_in[9];
    float* out = (float*)d_out;

    cudaFuncSetAttribute(integrate_kernel,
                         cudaFuncAttributeMaxDynamicSharedMemorySize, SMEM_BYTES);
    integrate_kernel<<<RC, 512, SMEM_BYTES>>>(tarr, y0, W1, b1, W2, b2, W3, b3);
    einsum_kernel<<<dim3(NXY / 256, 3), 256>>>(basis, out);
}

// round 8
// speedup vs baseline: 1.2073x; 1.2073x over previous
#include <cuda_runtime.h>
#include <cooperative_groups.h>
#include <math.h>

namespace cg = cooperative_groups;

#define DD 384
#define HH 128
#define KK 128
#define NT 32
#define NXY 65536
#define MB 8
#define NKNOT 5
#define RC 4            // cluster size
#define J1 (DD / RC)    // 96
#define J2 (HH / RC)    // 32
#define J3 (HH / RC)    // 32

// coeff scratch: [c][k][t], t contiguous
__device__ float g_coeff[3 * KK * NT];

// coarse knots (fine-grid indices): 4 steps
__constant__ int c_kn[NKNOT] = {0, 8, 16, 24, 31};

#define NW1 (J1 * HH)           // 12288
#define NW2 (J2 * HH)           // 4096
#define NW3 (J3 * DD)           // 12288
#define SMEM_FLOATS (NW1 + NW2 + NW3 + 8 * DD + 2 * HH + 4 * HH + HH + HH + DD)
#define SMEM_BYTES  (SMEM_FLOATS * 4)

__device__ __forceinline__ void store_coeff(int i, int n, float val) {
    int k = i / 3, c = i - 3 * k;
    g_coeff[(c * KK + k) * NT + n] = val;
}

struct Ctx {
    const float *sW1, *sW2, *sW3;   // float4-packed: [j/4][i][4]
    float *h1, *h2, *part, *red1, *red2, *red3;
    const float *red1p[RC], *red2p[RC], *red3p[RC];
    const float *b1, *b2, *b3;
    int r;
};

// vout = W3 * elu(W2 * relu(W1*vin + b1) + b2) + b3
// RC CTAs each hold a j-slice; DSMEM all-reduce of partials.
__device__ __forceinline__ void mlp(cg::cluster_group& cluster,
                                    const float* __restrict__ vin,
                                    float* __restrict__ vout,
                                    const Ctx& cx, int tid)
{
    const int i = tid & 127, p = tid >> 7;
    __syncthreads();                        // vin ready

    // ---- layer 1: local j-slice 96, p-split 4 x 24 (6 float4 steps) ----
    {
        const float4* w4 = (const float4*)cx.sW1;
        const float4* x4 = (const float4*)(vin + cx.r * J1);
        float a0 = 0.f, a1 = 0.f, a2 = 0.f, a3 = 0.f;
        #pragma unroll
        for (int j4 = p * 6; j4 < p * 6 + 6; j4++) {
            float4 w = w4[j4 * HH + i];
            float4 x = x4[j4];
            a0 = fmaf(w.x, x.x, a0);
            a1 = fmaf(w.y, x.y, a1);
            a2 = fmaf(w.z, x.z, a2);
            a3 = fmaf(w.w, x.w, a3);
        }
        cx.part[p * HH + i] = (a0 + a1) + (a2 + a3);
    }
    __syncthreads();
    if (tid < HH)
        cx.red1[tid] = (cx.part[tid] + cx.part[HH + tid])
                     + (cx.part[2 * HH + tid] + cx.part[3 * HH + tid]);
    cluster.sync();
    if (tid < HH) {
        float s = cx.b1[tid];
        #pragma unroll
        for (int rr = 0; rr < RC; rr++) s += cx.red1p[rr][tid];
        cx.h1[tid] = fmaxf(s, 0.f);
    }
    __syncthreads();

    // ---- layer 2: local j-slice 32, p-split 4 x 8 (2 float4 steps), ELU ----
    {
        const float4* w4 = (const float4*)cx.sW2;
        const float4* x4 = (const float4*)(cx.h1 + cx.r * J2);
        float a0 = 0.f, a1 = 0.f, a2 = 0.f, a3 = 0.f;
        #pragma unroll
        for (int j4 = p * 2; j4 < p * 2 + 2; j4++) {
            float4 w = w4[j4 * HH + i];
            float4 x = x4[j4];
            a0 = fmaf(w.x, x.x, a0);
            a1 = fmaf(w.y, x.y, a1);
            a2 = fmaf(w.z, x.z, a2);
            a3 = fmaf(w.w, x.w, a3);
        }
        cx.part[p * HH + i] = (a0 + a1) + (a2 + a3);
    }
    __syncthreads();
    if (tid < HH)
        cx.red2[tid] = (cx.part[tid] + cx.part[HH + tid])
                     + (cx.part[2 * HH + tid] + cx.part[3 * HH + tid]);
    cluster.sync();
    if (tid < HH) {
        float s = cx.b2[tid];
        #pragma unroll
        for (int rr = 0; rr < RC; rr++) s += cx.red2p[rr][tid];
        cx.h2[tid] = s > 0.f ? s : expm1f(s);
    }
    __syncthreads();

    // ---- layer 3: 384 outs, local j-slice 32 (8 float4 steps) ----
    if (tid < DD) {
        const float4* w4 = (const float4*)cx.sW3;
        const float4* x4 = (const float4*)(cx.h2 + cx.r * J3);
        float a0 = 0.f, a1 = 0.f, a2 = 0.f, a3 = 0.f;
        #pragma unroll
        for (int j4 = 0; j4 < 8; j4++) {
            float4 w = w4[j4 * DD + tid];
            float4 x = x4[j4];
            a0 = fmaf(w.x, x.x, a0);
            a1 = fmaf(w.y, x.y, a1);
            a2 = fmaf(w.z, x.z, a2);
            a3 = fmaf(w.w, x.w, a3);
        }
        cx.red3[tid] = (a0 + a1) + (a2 + a3);
    }
    cluster.sync();
    if (tid < DD) {
        float s = cx.b3[tid];
        #pragma unroll
        for (int rr = 0; rr < RC; rr++) s += cx.red3p[rr][tid];
        vout[tid] = s;
    }
    __syncthreads();
}

__global__ __launch_bounds__(512, 1) __cluster_dims__(RC, 1, 1)
void integrate_kernel(const float* __restrict__ tarr, const float* __restrict__ y0,
                      const float* __restrict__ W1, const float* __restrict__ b1,
                      const float* __restrict__ W2, const float* __restrict__ b2,
                      const float* __restrict__ W3, const float* __restrict__ b3)
{
    extern __shared__ float smf[];
    cg::cluster_group cluster = cg::this_cluster();
    const int tid = threadIdx.x;
    const int r = (int)cluster.block_rank();

    float* sW1 = smf;
    float* sW2 = sW1 + NW1;
    float* sW3 = sW2 + NW2;
    float* y    = sW3 + NW3;
    float* yold = y + DD;
    float* fold = yold + DD;
    float* v    = fold + DD;
    float* k1   = v + DD;
    float* k2   = k1 + DD;
    float* k3   = k2 + DD;
    float* k4   = k3 + DD;
    float* h1   = k4 + DD;
    float* h2   = h1 + HH;
    float* part = h2 + HH;
    float* red1 = part + 4 * HH;
    float* red2 = red1 + HH;
    float* red3 = red2 + HH;

    Ctx cx;
    cx.sW1 = sW1; cx.sW2 = sW2; cx.sW3 = sW3;
    cx.h1 = h1; cx.h2 = h2; cx.part = part;
    cx.red1 = red1; cx.red2 = red2; cx.red3 = red3;
    cx.b1 = b1; cx.b2 = b2; cx.b3 = b3; cx.r = r;
    #pragma unroll
    for (int rr = 0; rr < RC; rr++) {
        cx.red1p[rr] = (const float*)cluster.map_shared_rank(red1, rr);
        cx.red2p[rr] = (const float*)cluster.map_shared_rank(red2, rr);
        cx.red3p[rr] = (const float*)cluster.map_shared_rank(red3, rr);
    }

    // ---- preload weight slices, float4-packed [j/4][i][4] ----
    for (int idx = tid; idx < NW1; idx += 512) {
        int j4 = idx / (HH * 4), rem = idx - j4 * HH * 4;
        int i = rem >> 2, q = rem & 3;
        sW1[idx] = W1[i * DD + r * J1 + j4 * 4 + q];
    }
    for (int idx = tid; idx < NW2; idx += 512) {
        int j4 = idx / (HH * 4), rem = idx - j4 * HH * 4;
        int i = rem >> 2, q = rem & 3;
        sW2[idx] = W2[i * HH + r * J2 + j4 * 4 + q];
    }
    for (int idx = tid; idx < NW3; idx += 512) {
        int j4 = idx / (DD * 4), rem = idx - j4 * DD * 4;
        int i = rem >> 2, q = rem & 3;
        sW3[idx] = W3[i * HH + r * J3 + j4 * 4 + q];
    }

    for (int i = tid; i < DD; i += 512) {
        float val = y0[i];
        y[i] = val;
        if (r == 0) store_coeff(i, 0, val);
    }

    for (int s = 0; s < NKNOT; s++) {
        mlp(cluster, y, k1, cx, tid);

        if (s > 0 && r == 0) {
            const int n0 = c_kn[s - 1], n1 = c_kn[s];
            const float t0 = tarr[n0];
            const float hstep = tarr[n1] - t0;
            for (int n = n0 + 1; n < n1; n++) {
                const float th = (tarr[n] - t0) / hstep;
                const float th2 = th * th, th3 = th2 * th;
                const float cy0 = 1.f - 3.f * th2 + 2.f * th3;
                const float cy1 = 3.f * th2 - 2.f * th3;
                const float cf0 = hstep * (th - 2.f * th2 + th3);
                const float cf1 = hstep * (th3 - th2);
                for (int i = tid; i < DD; i += 512) {
                    float val = cy0 * yold[i] + cy1 * y[i]
                              + cf0 * fold[i] + cf1 * k1[i];
                    store_coeff(i, n, val);
                }
            }
            for (int i = tid; i < DD; i += 512)
                store_coeff(i, n1, y[i]);
        }
        if (s == NKNOT - 1) break;

        const float hstep = tarr[c_kn[s + 1]] - tarr[c_kn[s]];
        for (int i = tid; i < DD; i += 512) {
            yold[i] = y[i];
            fold[i] = k1[i];
            v[i] = y[i] + hstep * (1.f / 3.f) * k1[i];
        }

        mlp(cluster, v, k2, cx, tid);
        for (int i = tid; i < DD; i += 512)
            v[i] = y[i] + hstep * (k2[i] - (1.f / 3.f) * k1[i]);

        mlp(cluster, v, k3, cx, tid);
        for (int i = tid; i < DD; i += 512)
            v[i] = y[i] + hstep * (k1[i] - k2[i] + k3[i]);

        mlp(cluster, v, k4, cx, tid);
        for (int i = tid; i < DD; i += 512)
            y[i] = y[i] + hstep * 0.125f * (k1[i] + 3.f * (k2[i] + k3[i]) + k4[i]);
    }
}

// ================= einsum: cp.async-staged, float4 throughout ================
#define EPX 256          // px per CTA
#define ETH 256          // threads per CTA
#define CH 8             // k-rows per chunk
#define NCH (KK / CH)    // 16 chunks
#define ST 3             // pipeline stages
#define CHF (CH * EPX)   // 2048 floats per chunk buffer

__device__ __forceinline__ void cp16(float* s, const float* g) {
    unsigned sa = (unsigned)__cvta_generic_to_shared(s);
    asm volatile("cp.async.cg.shared.global [%0], [%1], 16;\n" :: "r"(sa), "l"(g));
}
__device__ __forceinline__ void cp_commit() {
    asm volatile("cp.async.commit_group;\n" ::: "memory");
}
template <int N>
__device__ __forceinline__ void cp_wait() {
    asm volatile("cp.async.wait_group %0;\n" :: "n"(N) : "memory");
}

__global__ __launch_bounds__(ETH)
void einsum_kernel(const float* __restrict__ basis, float* __restrict__ out)
{
    __shared__ __align__(16) float ckt[KK * NT];      // 16 KB: coeff[c], [k][t]
    __shared__ __align__(16) float buf[ST][CHF];      // 3 x 8 KB basis stages
    const int c = blockIdx.y;
    const int tid = threadIdx.x;
    const int pxg = tid & 63;          // 4-px group
    const int tg = tid >> 6;           // t-group (8 t's)
    const int xy0 = blockIdx.x * EPX;
    const size_t kst = (size_t)3 * NXY;
    const float* bbase = basis + (size_t)c * NXY + xy0;

    for (int i = tid; i < KK * NT; i += ETH)
        ckt[i] = g_coeff[c * KK * NT + i];

    // fill(ci, b): 512 float4 = 2 per thread
    auto fill = [&](int ci, int b) {
        #pragma unroll
        for (int h = 0; h < 2; h++) {
            int idx = tid + h * ETH;          // 0..511
            int row = idx >> 6, f = idx & 63; // 8 rows x 64 float4
            cp16(&buf[b][row * EPX + f * 4],
                 bbase + (size_t)(ci * CH + row) * kst + f * 4);
        }
    };

    #pragma unroll
    for (int pc = 0; pc < ST - 1; pc++) { fill(pc, pc); cp_commit(); }

    float4 acc[8];
    #pragma unroll
    for (int q = 0; q < 8; q++) acc[q] = make_float4(0.f, 0.f, 0.f, 0.f);

    for (int ci = 0; ci < NCH; ci++) {
        cp_wait<ST - 2>();
        __syncthreads();                    // chunk ci ready; prev buf reads done
        const int b = ci % ST;
        const float4* bs4 = (const float4*)buf[b];
        const float4* ck4 = (const float4*)ckt;
        #pragma unroll
        for (int kr = 0; kr < CH; kr++) {
            const int k = ci * CH + kr;
            const float4 bs = bs4[kr * (EPX / 4) + pxg];
            const float4 c0 = ck4[k * 8 + tg * 2];
            const float4 c1 = ck4[k * 8 + tg * 2 + 1];
            acc[0].x = fmaf(c0.x, bs.x, acc[0].x); acc[0].y = fmaf(c0.x, bs.y, acc[0].y);
            acc[0].z = fmaf(c0.x, bs.z, acc[0].z); acc[0].w = fmaf(c0.x, bs.w, acc[0].w);
            acc[1].x = fmaf(c0.y, bs.x, acc[1].x); acc[1].y = fmaf(c0.y, bs.y, acc[1].y);
            acc[1].z = fmaf(c0.y, bs.z, acc[1].z); acc[1].w = fmaf(c0.y, bs.w, acc[1].w);
            acc[2].x = fmaf(c0.z, bs.x, acc[2].x); acc[2].y = fmaf(c0.z, bs.y, acc[2].y);
            acc[2].z = fmaf(c0.z, bs.z, acc[2].z); acc[2].w = fmaf(c0.z, bs.w, acc[2].w);
            acc[3].x = fmaf(c0.w, bs.x, acc[3].x); acc[3].y = fmaf(c0.w, bs.y, acc[3].y);
            acc[3].z = fmaf(c0.w, bs.z, acc[3].z); acc[3].w = fmaf(c0.w, bs.w, acc[3].w);
            acc[4].x = fmaf(c1.x, bs.x, acc[4].x); acc[4].y = fmaf(c1.x, bs.y, acc[4].y);
            acc[4].z = fmaf(c1.x, bs.z, acc[4].z); acc[4].w = fmaf(c1.x, bs.w, acc[4].w);
            acc[5].x = fmaf(c1.y, bs.x, acc[5].x); acc[5].y = fmaf(c1.y, bs.y, acc[5].y);
            acc[5].z = fmaf(c1.y, bs.z, acc[5].z); acc[5].w = fmaf(c1.y, bs.w, acc[5].w);
            acc[6].x = fmaf(c1.z, bs.x, acc[6].x); acc[6].y = fmaf(c1.z, bs.y, acc[6].y);
            acc[6].z = fmaf(c1.z, bs.z, acc[6].z); acc[6].w = fmaf(c1.z, bs.w, acc[6].w);
            acc[7].x = fmaf(c1.w, bs.x, acc[7].x); acc[7].y = fmaf(c1.w, bs.y, acc[7].y);
            acc[7].z = fmaf(c1.w, bs.z, acc[7].z); acc[7].w = fmaf(c1.w, bs.w, acc[7].w);
        }
        __syncthreads();                    // done reading buf b
        const int nc = ci + ST - 1;
        if (nc < NCH) fill(nc, nc % ST);
        cp_commit();
    }

    // stores: thread owns 4 consecutive px x 8 t; replicate over m. STG.128.
    const int px = xy0 + pxg * 4;
    #pragma unroll
    for (int q = 0; q < 8; q++) {
        const int t = tg * 8 + q;
        float* base = out + ((size_t)(t * MB) * 3 + c) * NXY + px;
        #pragma unroll
        for (int m = 0; m < MB; m++)
            __stcs((float4*)(base + (size_t)m * (3 * NXY)), acc[q]);
    }
}

extern "C" void kernel_launch(void* const* d_in, const int* in_sizes, int n_in,
                              void* d_out, int out_size)
{
    // metadata order: grid0, t, init_coeffs, W1, b1, W2, b2, W3, b3, basis
    const float* tarr = (const float*)d_in[1];
    const float* y0   = (const float*)d_in[2];
    const float* W1   = (const float*)d_in[3];
    const float* b1   = (const float*)d_in[4];
    const float* W2   = (const float*)d_in[5];
    const float* b2   = (const float*)d_in[6];
    const float* W3   = (const float*)d_in[7];
    const float* b3   = (const float*)d_in[8];
    const float* basis = (const float*)d_in[9];
    float* out = (float*)d_out;

    cudaFuncSetAttribute(integrate_kernel,
                         cudaFuncAttributeMaxDynamicSharedMemorySize, SMEM_BYTES);
    integrate_kernel<<<RC, 512, SMEM_BYTES>>>(tarr, y0, W1, b1, W2, b2, W3, b3);
    einsum_kernel<<<dim3(NXY / EPX, 3), ETH>>>(basis, out);
}

// round 10
// speedup vs baseline: 1.3511x; 1.1191x over previous
#include <cuda_runtime.h>
#include <cooperative_groups.h>
#include <math.h>

namespace cg = cooperative_groups;

#define DD 384
#define HH 128
#define KK 128
#define NT 32
#define NXY 65536
#define MB 8
#define NKNOT 5
#define RC 4            // cluster size
#define NI1 32          // L1 output slice per CTA (4*32=128)
#define NI3 96          // L3 output slice per CTA (4*96=384)

// coeff scratch: [c][k][t], t contiguous
__device__ float g_coeff[3 * KK * NT];

// coarse knots (fine-grid indices): 4 steps
__constant__ int c_kn[NKNOT] = {0, 8, 16, 24, 31};

#define NW1 (NI1 * DD)          // 12288 (48KB)  [j4][i][4]
#define NW2 (HH * HH)           // 16384 (64KB)  [j4][i][4], full
#define NW3 (NI3 * HH)          // 12288 (48KB)  [j4][i][4]
#define SMEM_FLOATS (NW1 + NW2 + NW3 + 8 * DD + HH + HH + 512)
#define SMEM_BYTES  (SMEM_FLOATS * 4)

__device__ __forceinline__ void store_coeff(int i, int n, float val) {
    int k = i / 3, c = i - 3 * k;
    g_coeff[(c * KK + k) * NT + n] = val;
}

struct Ctx {
    const float *sW1, *sW2, *sW3;
    float *h1f, *h2, *part;
    float *h1p[RC];                 // peer h1f
    const float *b1, *b2, *b3;
    int r;
};

// vout = W3 * elu(W2 * relu(W1*vin + b1) + b2) + b3
// i-sliced L1/L3, full local L2. Gathers via DSMEM remote stores + 2 cluster.syncs.
// voutp[rr] = peer pointers to this eval's target k-buffer.
__device__ __forceinline__ void mlp(cg::cluster_group& cluster,
                                    const float* __restrict__ vin,
                                    float* const* voutp,
                                    const Ctx& cx, int tid)
{
    __syncthreads();                        // vin ready

    // ---- layer 1: 32 local outputs, full j=384. i=tid&31, p=tid>>5 (16) ----
    {
        const int i = tid & 31, p = tid >> 5;
        const float4* w4 = (const float4*)cx.sW1;
        const float4* x4 = (const float4*)vin;
        float a0 = 0.f, a1 = 0.f, a2 = 0.f, a3 = 0.f;
        #pragma unroll
        for (int j4 = p * 6; j4 < p * 6 + 6; j4++) {
            float4 w = w4[j4 * NI1 + i];
            float4 x = x4[j4];
            a0 = fmaf(w.x, x.x, a0);
            a1 = fmaf(w.y, x.y, a1);
            a2 = fmaf(w.z, x.z, a2);
            a3 = fmaf(w.w, x.w, a3);
        }
        cx.part[p * NI1 + i] = (a0 + a1) + (a2 + a3);
    }
    __syncthreads();
    if (tid < NI1) {
        float s = cx.b1[cx.r * NI1 + tid];
        #pragma unroll
        for (int pp = 0; pp < 16; pp++) s += cx.part[pp * NI1 + tid];
        s = fmaxf(s, 0.f);
        #pragma unroll
        for (int rr = 0; rr < RC; rr++) cx.h1p[rr][cx.r * NI1 + tid] = s;
    }
    cluster.sync();

    // ---- layer 2: full 128 outputs local. i=tid&127, p=tid>>7 (4), ELU ----
    {
        const int i = tid & 127, p = tid >> 7;
        const float4* w4 = (const float4*)cx.sW2;
        const float4* x4 = (const float4*)cx.h1f;
        float a0 = 0.f, a1 = 0.f, a2 = 0.f, a3 = 0.f;
        #pragma unroll
        for (int j4 = p * 8; j4 < p * 8 + 8; j4++) {
            float4 w = w4[j4 * HH + i];
            float4 x = x4[j4];
            a0 = fmaf(w.x, x.x, a0);
            a1 = fmaf(w.y, x.y, a1);
            a2 = fmaf(w.z, x.z, a2);
            a3 = fmaf(w.w, x.w, a3);
        }
        cx.part[p * HH + i] = (a0 + a1) + (a2 + a3);
    }
    __syncthreads();
    if (tid < HH) {
        float s = cx.b2[tid] + cx.part[tid] + cx.part[HH + tid]
                + cx.part[2 * HH + tid] + cx.part[3 * HH + tid];
        cx.h2[tid] = s > 0.f ? s : expm1f(s);
    }
    __syncthreads();

    // ---- layer 3: 96 local outputs, j=128. tid<384: i=tid%96, p=tid/96 ----
    if (tid < 384) {
        const int i = tid % NI3, p = tid / NI3;
        const float4* w4 = (const float4*)cx.sW3;
        const float4* x4 = (const float4*)cx.h2;
        float a0 = 0.f, a1 = 0.f, a2 = 0.f, a3 = 0.f;
        #pragma unroll
        for (int j4 = p * 8; j4 < p * 8 + 8; j4++) {
            float4 w = w4[j4 * NI3 + i];
            float4 x = x4[j4];
            a0 = fmaf(w.x, x.x, a0);
            a1 = fmaf(w.y, x.y, a1);
            a2 = fmaf(w.z, x.z, a2);
            a3 = fmaf(w.w, x.w, a3);
        }
        cx.part[p * NI3 + i] = (a0 + a1) + (a2 + a3);
    }
    __syncthreads();
    if (tid < NI3) {
        float s = cx.b3[cx.r * NI3 + tid] + cx.part[tid] + cx.part[NI3 + tid]
                + cx.part[2 * NI3 + tid] + cx.part[3 * NI3 + tid];
        #pragma unroll
        for (int rr = 0; rr < RC; rr++) voutp[rr][cx.r * NI3 + tid] = s;
    }
    cluster.sync();
}

__global__ __launch_bounds__(512, 1) __cluster_dims__(RC, 1, 1)
void integrate_kernel(const float* __restrict__ tarr, const float* __restrict__ y0,
                      const float* __restrict__ W1, const float* __restrict__ b1,
                      const float* __restrict__ W2, const float* __restrict__ b2,
                      const float* __restrict__ W3, const float* __restrict__ b3)
{
    extern __shared__ float smf[];
    cg::cluster_group cluster = cg::this_cluster();
    const int tid = threadIdx.x;
    const int r = (int)cluster.block_rank();

    float* sW1 = smf;
    float* sW2 = sW1 + NW1;
    float* sW3 = sW2 + NW2;
    float* y    = sW3 + NW3;
    float* yold = y + DD;
    float* fold = yold + DD;
    float* v    = fold + DD;
    float* k1   = v + DD;
    float* k2   = k1 + DD;
    float* k3   = k2 + DD;
    float* k4   = k3 + DD;
    float* h1f  = k4 + DD;
    float* h2   = h1f + HH;
    float* part = h2 + HH;

    Ctx cx;
    cx.sW1 = sW1; cx.sW2 = sW2; cx.sW3 = sW3;
    cx.h1f = h1f; cx.h2 = h2; cx.part = part;
    cx.b1 = b1; cx.b2 = b2; cx.b3 = b3; cx.r = r;
    float* k1p[RC]; float* k2p[RC]; float* k3p[RC]; float* k4p[RC];
    #pragma unroll
    for (int rr = 0; rr < RC; rr++) {
        cx.h1p[rr] = (float*)cluster.map_shared_rank(h1f, rr);
        k1p[rr] = (float*)cluster.map_shared_rank(k1, rr);
        k2p[rr] = (float*)cluster.map_shared_rank(k2, rr);
        k3p[rr] = (float*)cluster.map_shared_rank(k3, rr);
        k4p[rr] = (float*)cluster.map_shared_rank(k4, rr);
    }

    // ---- preload weight slices, float4-packed [j4][i][4] ----
    for (int idx = tid; idx < NW1; idx += 512) {
        int j4 = idx >> 7, rem = idx & 127, i = rem >> 2, q = rem & 3;
        sW1[idx] = W1[(r * NI1 + i) * DD + j4 * 4 + q];
    }
    for (int idx = tid; idx < NW2; idx += 512) {
        int j4 = idx >> 9, rem = idx & 511, i = rem >> 2, q = rem & 3;
        sW2[idx] = W2[i * HH + j4 * 4 + q];
    }
    for (int idx = tid; idx < NW3; idx += 512) {
        int j4 = idx / 384, rem = idx - j4 * 384, i = rem >> 2, q = rem & 3;
        sW3[idx] = W3[(r * NI3 + i) * HH + j4 * 4 + q];
    }

    for (int i = tid; i < DD; i += 512) {
        float val = y0[i];
        y[i] = val;
        if (r == 0) store_coeff(i, 0, val);
    }

    for (int s = 0; s < NKNOT; s++) {
        mlp(cluster, y, k1p, cx, tid);

        if (s > 0 && r == 0) {
            const int n0 = c_kn[s - 1], n1 = c_kn[s];
            const float t0 = tarr[n0];
            const float hstep = tarr[n1] - t0;
            for (int n = n0 + 1; n < n1; n++) {
                const float th = (tarr[n] - t0) / hstep;
                const float th2 = th * th, th3 = th2 * th;
                const float cy0 = 1.f - 3.f * th2 + 2.f * th3;
                const float cy1 = 3.f * th2 - 2.f * th3;
                const float cf0 = hstep * (th - 2.f * th2 + th3);
                const float cf1 = hstep * (th3 - th2);
                for (int i = tid; i < DD; i += 512) {
                    float val = cy0 * yold[i] + cy1 * y[i]
                              + cf0 * fold[i] + cf1 * k1[i];
                    store_coeff(i, n, val);
                }
            }
            for (int i = tid; i < DD; i += 512)
                store_coeff(i, n1, y[i]);
        }
        if (s == NKNOT - 1) break;

        const float hstep = tarr[c_kn[s + 1]] - tarr[c_kn[s]];
        for (int i = tid; i < DD; i += 512) {
            yold[i] = y[i];
            fold[i] = k1[i];
            v[i] = y[i] + hstep * (1.f / 3.f) * k1[i];
        }

        mlp(cluster, v, k2p, cx, tid);
        for (int i = tid; i < DD; i += 512)
            v[i] = y[i] + hstep * (k2[i] - (1.f / 3.f) * k1[i]);

        mlp(cluster, v, k3p, cx, tid);
        for (int i = tid; i < DD; i += 512)
            v[i] = y[i] + hstep * (k1[i] - k2[i] + k3[i]);

        mlp(cluster, v, k4p, cx, tid);
        for (int i = tid; i < DD; i += 512)
            y[i] = y[i] + hstep * 0.125f * (k1[i] + 3.f * (k2[i] + k3[i]) + k4[i]);
    }
}

// ================= einsum: cp.async-staged, 128-thread CTAs ================
#define EPX 128          // px per CTA
#define ETH 128          // threads per CTA
#define CH 8             // k-rows per chunk
#define NCH (KK / CH)    // 16 chunks
#define ST 3             // pipeline stages
#define CHF (CH * EPX)   // 1024 floats per chunk buffer

__device__ __forceinline__ void cp16(float* s, const float* g) {
    unsigned sa = (unsigned)__cvta_generic_to_shared(s);
    asm volatile("cp.async.cg.shared.global [%0], [%1], 16;\n" :: "r"(sa), "l"(g));
}
__device__ __forceinline__ void cp_commit() {
    asm volatile("cp.async.commit_group;\n" ::: "memory");
}
template <int N>
__device__ __forceinline__ void cp_wait() {
    asm volatile("cp.async.wait_group %0;\n" :: "n"(N) : "memory");
}

__global__ __launch_bounds__(ETH, 7)
void einsum_kernel(const float* __restrict__ basis, float* __restrict__ out)
{
    __shared__ __align__(16) float ckt[KK * NT];      // 16 KB: coeff[c], [k][t]
    __shared__ __align__(16) float buf[ST][CHF];      // 3 x 4 KB basis stages
    const int c = blockIdx.y;
    const int tid = threadIdx.x;
    const int pxg = tid & 31;          // 4-px group (32 groups = 128 px)
    const int tg = tid >> 5;           // t-group: 4 groups x 8 t
    const int xy0 = blockIdx.x * EPX;
    const size_t kst = (size_t)3 * NXY;
    const float* bbase = basis + (size_t)c * NXY + xy0;

    {   // ckt load: 1024 float4, 8 per thread
        const float4* src = (const float4*)(g_coeff + c * KK * NT);
        float4* dst = (float4*)ckt;
        #pragma unroll
        for (int h = 0; h < 8; h++) dst[tid + h * ETH] = src[tid + h * ETH];
    }

    auto fill = [&](int ci, int b) {
        #pragma unroll
        for (int h = 0; h < 2; h++) {
            int idx = tid + h * ETH;          // 0..255
            int row = idx >> 5, f = idx & 31; // 8 rows x 32 float4
            cp16(&buf[b][row * EPX + f * 4],
                 bbase + (size_t)(ci * CH + row) * kst + f * 4);
        }
    };

    #pragma unroll
    for (int pc = 0; pc < ST - 1; pc++) { fill(pc, pc); cp_commit(); }

    float4 acc[8];
    #pragma unroll
    for (int q = 0; q < 8; q++) acc[q] = make_float4(0.f, 0.f, 0.f, 0.f);

    for (int ci = 0; ci < NCH; ci++) {
        cp_wait<ST - 2>();
        __syncthreads();                    // chunk ci ready; prev buf reads done
        const int b = ci % ST;
        const float4* bs4 = (const float4*)buf[b];
        const float4* ck4 = (const float4*)ckt;
        #pragma unroll
        for (int kr = 0; kr < CH; kr++) {
            const int k = ci * CH + kr;
            const float4 bs = bs4[kr * (EPX / 4) + pxg];
            const float4 c0 = ck4[k * 8 + tg * 2];
            const float4 c1 = ck4[k * 8 + tg * 2 + 1];
            acc[0].x = fmaf(c0.x, bs.x, acc[0].x); acc[0].y = fmaf(c0.x, bs.y, acc[0].y);
            acc[0].z = fmaf(c0.x, bs.z, acc[0].z); acc[0].w = fmaf(c0.x, bs.w, acc[0].w);
            acc[1].x = fmaf(c0.y, bs.x, acc[1].x); acc[1].y = fmaf(c0.y, bs.y, acc[1].y);
            acc[1].z = fmaf(c0.y, bs.z, acc[1].z); acc[1].w = fmaf(c0.y, bs.w, acc[1].w);
            acc[2].x = fmaf(c0.z, bs.x, acc[2].x); acc[2].y = fmaf(c0.z, bs.y, acc[2].y);
            acc[2].z = fmaf(c0.z, bs.z, acc[2].z); acc[2].w = fmaf(c0.z, bs.w, acc[2].w);
            acc[3].x = fmaf(c0.w, bs.x, acc[3].x); acc[3].y = fmaf(c0.w, bs.y, acc[3].y);
            acc[3].z = fmaf(c0.w, bs.z, acc[3].z); acc[3].w = fmaf(c0.w, bs.w, acc[3].w);
            acc[4].x = fmaf(c1.x, bs.x, acc[4].x); acc[4].y = fmaf(c1.x, bs.y, acc[4].y);
            acc[4].z = fmaf(c1.x, bs.z, acc[4].z); acc[4].w = fmaf(c1.x, bs.w, acc[4].w);
            acc[5].x = fmaf(c1.y, bs.x, acc[5].x); acc[5].y = fmaf(c1.y, bs.y, acc[5].y);
            acc[5].z = fmaf(c1.y, bs.z, acc[5].z); acc[5].w = fmaf(c1.y, bs.w, acc[5].w);
            acc[6].x = fmaf(c1.z, bs.x, acc[6].x); acc[6].y = fmaf(c1.z, bs.y, acc[6].y);
            acc[6].z = fmaf(c1.z, bs.z, acc[6].z); acc[6].w = fmaf(c1.z, bs.w, acc[6].w);
            acc[7].x = fmaf(c1.w, bs.x, acc[7].x); acc[7].y = fmaf(c1.w, bs.y, acc[7].y);
            acc[7].z = fmaf(c1.w, bs.z, acc[7].z); acc[7].w = fmaf(c1.w, bs.w, acc[7].w);
        }
        __syncthreads();                    // done reading buf b
        const int nc = ci + ST - 1;
        if (nc < NCH) fill(nc, nc % ST);
        cp_commit();
    }

    // stores: thread owns 4 consecutive px x 8 t; replicate over m. STG.128.
    const int px = xy0 + pxg * 4;
    #pragma unroll
    for (int q = 0; q < 8; q++) {
        const int t = tg * 8 + q;
        float* base = out + ((size_t)(t * MB) * 3 + c) * NXY + px;
        #pragma unroll
        for (int m = 0; m < MB; m++)
            __stcs((float4*)(base + (size_t)m * (3 * NXY)), acc[q]);
    }
}

extern "C" void kernel_launch(void* const* d_in, const int* in_sizes, int n_in,
                              void* d_out, int out_size)
{
    // metadata order: grid0, t, init_coeffs, W1, b1, W2, b2, W3, b3, basis
    const float* tarr = (const float*)d_in[1];
    const float* y0   = (const float*)d_in[2];
    const float* W1   = (const float*)d_in[3];
    const float* b1   = (const float*)d_in[4];
    const float* W2   = (const float*)d_in[5];
    const float* b2   = (const float*)d_in[6];
    const float* W3   = (const float*)d_in[7];
    const float* b3   = (const float*)d_in[8];
    const float* basis = (const float*)d_in[9];
    float* out = (float*)d_out;

    cudaFuncSetAttribute(integrate_kernel,
                         cudaFuncAttributeMaxDynamicSharedMemorySize, SMEM_BYTES);
    integrate_kernel<<<RC, 512, SMEM_BYTES>>>(tarr, y0, W1, b1, W2, b2, W3, b3);
    einsum_kernel<<<dim3(NXY / EPX, 3), ETH>>>(basis, out);
}

// round 11
// speedup vs baseline: 1.4808x; 1.0960x over previous
#include <cuda_runtime.h>
#include <cooperative_groups.h>
#include <math.h>

namespace cg = cooperative_groups;

#define DD 384
#define HH 128
#define KK 128
#define NT 32
#define NXY 65536
#define MB 8
#define NKNOT 4
#define RC 4            // cluster size
#define NI1 32          // L1 output slice per CTA (4*32=128)
#define NI3 96          // L3 output slice per CTA (4*96=384)

// coeff scratch: [c][k][t], t contiguous
__device__ float g_coeff[3 * KK * NT];

// coarse knots (fine-grid indices): 3 steps
__constant__ int c_kn[NKNOT] = {0, 11, 21, 31};

#define NW1 (NI1 * DD)          // 12288 floats (48KB), float4-swizzled [j4][i^]
#define NW2 (HH * HH)           // 16384 (64KB)
#define NW3 (NI3 * HH)          // 12288 (48KB)
#define SMEM_FLOATS (NW1 + NW2 + NW3 + 8 * DD + HH + HH + 512)
#define SMEM_BYTES  (SMEM_FLOATS * 4)

__device__ __forceinline__ void store_coeff(int i, int n, float val) {
    int k = i / 3, c = i - 3 * k;
    g_coeff[(c * KK + k) * NT + n] = val;
}

// bank swizzle for [j4][i] float4 layouts: i' = i ^ (j4 & 31)
__device__ __forceinline__ int swz(int j4, int i, int ni) {
    return j4 * ni + (i ^ (j4 & 31));
}

struct Ctx {
    const float4 *sW1, *sW2, *sW3;
    float *h1f, *h2, *part;
    float *h1p[RC];                 // peer h1f
    const float *b1, *b2, *b3;
    int r;
};

// vout = W3 * elu(W2 * relu(W1*vin + b1) + b2) + b3
// i-sliced L1/L3, full local L2. Gathers via DSMEM remote stores + 2 cluster.syncs.
__device__ __forceinline__ void mlp(cg::cluster_group& cluster,
                                    const float* __restrict__ vin,
                                    float* const* voutp,
                                    const Ctx& cx, int tid)
{
    __syncthreads();                        // vin ready

    // ---- layer 1: 32 local outputs, full j=384. i=tid&31, p=tid>>5 (16) ----
    {
        const int i = tid & 31, p = tid >> 5;
        const float4* x4 = (const float4*)vin;
        float a0 = 0.f, a1 = 0.f, a2 = 0.f, a3 = 0.f;
        #pragma unroll
        for (int j4 = p * 6; j4 < p * 6 + 6; j4++) {
            float4 w = cx.sW1[swz(j4, i, NI1)];
            float4 x = x4[j4];
            a0 = fmaf(w.x, x.x, a0);
            a1 = fmaf(w.y, x.y, a1);
            a2 = fmaf(w.z, x.z, a2);
            a3 = fmaf(w.w, x.w, a3);
        }
        cx.part[p * NI1 + i] = (a0 + a1) + (a2 + a3);
    }
    __syncthreads();
    if (tid < NI1) {
        float s = cx.b1[cx.r * NI1 + tid];
        #pragma unroll
        for (int pp = 0; pp < 16; pp++) s += cx.part[pp * NI1 + tid];
        s = fmaxf(s, 0.f);
        #pragma unroll
        for (int rr = 0; rr < RC; rr++) cx.h1p[rr][cx.r * NI1 + tid] = s;
    }
    cluster.sync();

    // ---- layer 2: full 128 outputs local. i=tid&127, p=tid>>7 (4), ELU ----
    {
        const int i = tid & 127, p = tid >> 7;
        const float4* x4 = (const float4*)cx.h1f;
        float a0 = 0.f, a1 = 0.f, a2 = 0.f, a3 = 0.f;
        #pragma unroll
        for (int j4 = p * 8; j4 < p * 8 + 8; j4++) {
            float4 w = cx.sW2[swz(j4, i, HH)];
            float4 x = x4[j4];
            a0 = fmaf(w.x, x.x, a0);
            a1 = fmaf(w.y, x.y, a1);
            a2 = fmaf(w.z, x.z, a2);
            a3 = fmaf(w.w, x.w, a3);
        }
        cx.part[p * HH + i] = (a0 + a1) + (a2 + a3);
    }
    __syncthreads();
    if (tid < HH) {
        float s = cx.b2[tid] + cx.part[tid] + cx.part[HH + tid]
                + cx.part[2 * HH + tid] + cx.part[3 * HH + tid];
        cx.h2[tid] = s > 0.f ? s : expm1f(s);
    }
    __syncthreads();

    // ---- layer 3: 96 local outputs, j=128. tid<384: i=tid%96, p=tid/96 ----
    if (tid < 384) {
        const int i = tid % NI3, p = tid / NI3;
        const float4* x4 = (const float4*)cx.h2;
        float a0 = 0.f, a1 = 0.f, a2 = 0.f, a3 = 0.f;
        #pragma unroll
        for (int j4 = p * 8; j4 < p * 8 + 8; j4++) {
            float4 w = cx.sW3[swz(j4, i, NI3)];
            float4 x = x4[j4];
            a0 = fmaf(w.x, x.x, a0);
            a1 = fmaf(w.y, x.y, a1);
            a2 = fmaf(w.z, x.z, a2);
            a3 = fmaf(w.w, x.w, a3);
        }
        cx.part[p * NI3 + i] = (a0 + a1) + (a2 + a3);
    }
    __syncthreads();
    if (tid < NI3) {
        float s = cx.b3[cx.r * NI3 + tid] + cx.part[tid] + cx.part[NI3 + tid]
                + cx.part[2 * NI3 + tid] + cx.part[3 * NI3 + tid];
        #pragma unroll
        for (int rr = 0; rr < RC; rr++) voutp[rr][cx.r * NI3 + tid] = s;
    }
    cluster.sync();
}

__global__ __launch_bounds__(512, 1) __cluster_dims__(RC, 1, 1)
void integrate_kernel(const float* __restrict__ tarr, const float* __restrict__ y0,
                      const float* __restrict__ W1, const float* __restrict__ b1,
                      const float* __restrict__ W2, const float* __restrict__ b2,
                      const float* __restrict__ W3, const float* __restrict__ b3)
{
    extern __shared__ float smf[];
    cg::cluster_group cluster = cg::this_cluster();
    const int tid = threadIdx.x;
    const int r = (int)cluster.block_rank();

    float4* sW1 = (float4*)smf;
    float4* sW2 = sW1 + NW1 / 4;
    float4* sW3 = sW2 + NW2 / 4;
    float* y    = smf + NW1 + NW2 + NW3;
    float* yold = y + DD;
    float* fold = yold + DD;
    float* v    = fold + DD;
    float* k1   = v + DD;
    float* k2   = k1 + DD;
    float* k3   = k2 + DD;
    float* k4   = k3 + DD;
    float* h1f  = k4 + DD;
    float* h2   = h1f + HH;
    float* part = h2 + HH;

    Ctx cx;
    cx.sW1 = sW1; cx.sW2 = sW2; cx.sW3 = sW3;
    cx.h1f = h1f; cx.h2 = h2; cx.part = part;
    cx.b1 = b1; cx.b2 = b2; cx.b3 = b3; cx.r = r;
    float* k1p[RC]; float* k2p[RC]; float* k3p[RC]; float* k4p[RC];
    #pragma unroll
    for (int rr = 0; rr < RC; rr++) {
        cx.h1p[rr] = (float*)cluster.map_shared_rank(h1f, rr);
        k1p[rr] = (float*)cluster.map_shared_rank(k1, rr);
        k2p[rr] = (float*)cluster.map_shared_rank(k2, rr);
        k3p[rr] = (float*)cluster.map_shared_rank(k3, rr);
        k4p[rr] = (float*)cluster.map_shared_rank(k4, rr);
    }

    // ---- preload: coalesced LDG.128, swizzled STS.128 ----
    {
        const float4* W1f4 = (const float4*)W1;   // [128][96]
        for (int idx4 = tid; idx4 < NW1 / 4; idx4 += 512) {
            int i = idx4 / 96, j4 = idx4 - i * 96;
            sW1[swz(j4, i, NI1)] = W1f4[(r * NI1 + i) * 96 + j4];
        }
        const float4* W2f4 = (const float4*)W2;   // [128][32]
        for (int idx4 = tid; idx4 < NW2 / 4; idx4 += 512) {
            int i = idx4 >> 5, j4 = idx4 & 31;
            sW2[swz(j4, i, HH)] = W2f4[idx4];
        }
        const float4* W3f4 = (const float4*)W3;   // [384][32]
        for (int idx4 = tid; idx4 < NW3 / 4; idx4 += 512) {
            int i = idx4 >> 5, j4 = idx4 & 31;
            sW3[swz(j4, i, NI3)] = W3f4[(r * NI3 + i) * 32 + j4];
        }
    }

    for (int i = tid; i < DD; i += 512) {
        float val = y0[i];
        y[i] = val;
        if (r == 0) store_coeff(i, 0, val);
    }

    for (int s = 0; s < NKNOT; s++) {
        mlp(cluster, y, k1p, cx, tid);

        if (s > 0 && r == 0) {
            const int n0 = c_kn[s - 1], n1 = c_kn[s];
            const float t0 = tarr[n0];
            const float hstep = tarr[n1] - t0;
            for (int n = n0 + 1; n < n1; n++) {
                const float th = (tarr[n] - t0) / hstep;
                const float th2 = th * th, th3 = th2 * th;
                const float cy0 = 1.f - 3.f * th2 + 2.f * th3;
                const float cy1 = 3.f * th2 - 2.f * th3;
                const float cf0 = hstep * (th - 2.f * th2 + th3);
                const float cf1 = hstep * (th3 - th2);
                for (int i = tid; i < DD; i += 512) {
                    float val = cy0 * yold[i] + cy1 * y[i]
                              + cf0 * fold[i] + cf1 * k1[i];
                    store_coeff(i, n, val);
                }
            }
            for (int i = tid; i < DD; i += 512)
                store_coeff(i, n1, y[i]);
        }
        if (s == NKNOT - 1) break;

        const float hstep = tarr[c_kn[s + 1]] - tarr[c_kn[s]];
        for (int i = tid; i < DD; i += 512) {
            yold[i] = y[i];
            fold[i] = k1[i];
            v[i] = y[i] + hstep * (1.f / 3.f) * k1[i];
        }

        mlp(cluster, v, k2p, cx, tid);
        for (int i = tid; i < DD; i += 512)
            v[i] = y[i] + hstep * (k2[i] - (1.f / 3.f) * k1[i]);

        mlp(cluster, v, k3p, cx, tid);
        for (int i = tid; i < DD; i += 512)
            v[i] = y[i] + hstep * (k1[i] - k2[i] + k3[i]);

        mlp(cluster, v, k4p, cx, tid);
        for (int i = tid; i < DD; i += 512)
            y[i] = y[i] + hstep * 0.125f * (k1[i] + 3.f * (k2[i] + k3[i]) + k4[i]);
    }
}

// ============ einsum: cp.async-staged, packed fma.rn.f32x2 ============
#define EPX 128          // px per CTA
#define ETH 128          // threads per CTA
#define CH 8             // k-rows per chunk
#define NCH (KK / CH)    // 16 chunks
#define ST 3             // pipeline stages
#define CHF (CH * EPX)   // 1024 floats per chunk buffer

__device__ __forceinline__ void cp16(float* s, const float* g) {
    unsigned sa = (unsigned)__cvta_generic_to_shared(s);
    asm volatile("cp.async.cg.shared.global [%0], [%1], 16;\n" :: "r"(sa), "l"(g));
}
__device__ __forceinline__ void cp_commit() {
    asm volatile("cp.async.commit_group;\n" ::: "memory");
}
template <int N>
__device__ __forceinline__ void cp_wait() {
    asm volatile("cp.async.wait_group %0;\n" :: "n"(N) : "memory");
}
__device__ __forceinline__ void fma2(unsigned long long& d,
                                     unsigned long long a, unsigned long long b) {
    asm("fma.rn.f32x2 %0, %1, %2, %0;" : "+l"(d) : "l"(a), "l"(b));
}
__device__ __forceinline__ unsigned long long dup2(float x) {
    unsigned long long d;
    asm("mov.b64 %0, {%1, %1};" : "=l"(d) : "r"(__float_as_uint(x)));
    return d;
}

__global__ __launch_bounds__(ETH, 7)
void einsum_kernel(const float* __restrict__ basis, float* __restrict__ out)
{
    __shared__ __align__(16) float ckt[KK * NT];      // 16 KB: coeff[c], [k][t]
    __shared__ __align__(16) float buf[ST][CHF];      // 3 x 4 KB basis stages
    const int c = blockIdx.y;
    const int tid = threadIdx.x;
    const int pxg = tid & 31;          // 4-px group (32 groups = 128 px)
    const int tg = tid >> 5;           // t-group: 4 groups x 8 t
    const int xy0 = blockIdx.x * EPX;
    const size_t kst = (size_t)3 * NXY;
    const float* bbase = basis + (size_t)c * NXY + xy0;

    {   // ckt load: 1024 float4, 8 per thread
        const float4* src = (const float4*)(g_coeff + c * KK * NT);
        float4* dst = (float4*)ckt;
        #pragma unroll
        for (int h = 0; h < 8; h++) dst[tid + h * ETH] = src[tid + h * ETH];
    }

    auto fill = [&](int ci, int b) {
        #pragma unroll
        for (int h = 0; h < 2; h++) {
            int idx = tid + h * ETH;          // 0..255
            int row = idx >> 5, f = idx & 31; // 8 rows x 32 float4
            cp16(&buf[b][row * EPX + f * 4],
                 bbase + (size_t)(ci * CH + row) * kst + f * 4);
        }
    };

    #pragma unroll
    for (int pc = 0; pc < ST - 1; pc++) { fill(pc, pc); cp_commit(); }

    // acc[tp][px]: tp = t-pair (t=2*tp, 2*tp+1 within this tg's 8 t's), px 0..3
    unsigned long long acc[4][4];
    #pragma unroll
    for (int a = 0; a < 4; a++)
        #pragma unroll
        for (int b = 0; b < 4; b++) acc[a][b] = 0ull;

    const ulonglong2* ckp2 = (const ulonglong2*)ckt;  // c-pairs (t0t1),(t2t3)...

    for (int ci = 0; ci < NCH; ci++) {
        cp_wait<ST - 2>();
        __syncthreads();                    // chunk ci ready; prev buf reads done
        const int b = ci % ST;
        const float4* bs4 = (const float4*)buf[b];
        #pragma unroll
        for (int kr = 0; kr < CH; kr++) {
            const int k = ci * CH + kr;
            const float4 bs = bs4[kr * (EPX / 4) + pxg];
            const unsigned long long b0 = dup2(bs.x), b1 = dup2(bs.y);
            const unsigned long long b2 = dup2(bs.z), b3 = dup2(bs.w);
            const ulonglong2 cA = ckp2[k * 8 + tg * 2];      // (c_t0t1, c_t2t3)
            const ulonglong2 cB = ckp2[k * 8 + tg * 2 + 1];  // (c_t4t5, c_t6t7)
            fma2(acc[0][0], cA.x, b0); fma2(acc[0][1], cA.x, b1);
            fma2(acc[0][2], cA.x, b2); fma2(acc[0][3], cA.x, b3);
            fma2(acc[1][0], cA.y, b0); fma2(acc[1][1], cA.y, b1);
            fma2(acc[1][2], cA.y, b2); fma2(acc[1][3], cA.y, b3);
            fma2(acc[2][0], cB.x, b0); fma2(acc[2][1], cB.x, b1);
            fma2(acc[2][2], cB.x, b2); fma2(acc[2][3], cB.x, b3);
            fma2(acc[3][0], cB.y, b0); fma2(acc[3][1], cB.y, b1);
            fma2(acc[3][2], cB.y, b2); fma2(acc[3][3], cB.y, b3);
        }
        __syncthreads();                    // done reading buf b
        const int nc = ci + ST - 1;
        if (nc < NCH) fill(nc, nc % ST);
        cp_commit();
    }

    // stores: thread owns 4 consecutive px x 8 t; replicate over m. STG.128.
    const int px = xy0 + pxg * 4;
    #pragma unroll
    for (int tp = 0; tp < 4; tp++) {
        float2 p0 = *(float2*)&acc[tp][0];
        float2 p1 = *(float2*)&acc[tp][1];
        float2 p2 = *(float2*)&acc[tp][2];
        float2 p3 = *(float2*)&acc[tp][3];
        #pragma unroll
        for (int hi = 0; hi < 2; hi++) {
            const int t = tg * 8 + tp * 2 + hi;
            float4 v4 = hi ? make_float4(p0.y, p1.y, p2.y, p3.y)
                           : make_float4(p0.x, p1.x, p2.x, p3.x);
            float* base = out + ((size_t)(t * MB) * 3 + c) * NXY + px;
            #pragma unroll
            for (int m = 0; m < MB; m++)
                __stcs((float4*)(base + (size_t)m * (3 * NXY)), v4);
        }
    }
}

extern "C" void kernel_launch(void* const* d_in, const int* in_sizes, int n_in,
                              void* d_out, int out_size)
{
    // metadata order: grid0, t, init_coeffs, W1, b1, W2, b2, W3, b3, basis
    const float* tarr = (const float*)d_in[1];
    const float* y0   = (const float*)d_in[2];
    const float* W1   = (const float*)d_in[3];
    const float* b1   = (const float*)d_in[4];
    const float* W2   = (const float*)d_in[5];
    const float* b2   = (const float*)d_in[6];
    const float* W3   = (const float*)d_in[7];
    const float* b3   = (const float*)d_in[8];
    const float* basis = (const float*)d_in[9];
    float* out = (float*)d_out;

    cudaFuncSetAttribute(integrate_kernel,
                         cudaFuncAttributeMaxDynamicSharedMemorySize, SMEM_BYTES);
    integrate_kernel<<<RC, 512, SMEM_BYTES>>>(tarr, y0, W1, b1, W2, b2, W3, b3);
    einsum_kernel<<<dim3(NXY / EPX, 3), ETH>>>(basis, out);
}